// round 17
// baseline (speedup 1.0000x reference)
#include <cuda_runtime.h>

// residual = K3 * (K2 * (K1 * x)), depthwise, per-stage zero padding.
// Register-rolling column strips, 36-step unrolled pipeline, one launch.
// R14 scalar dataflow with two structural changes:
//  (a) input ring holds only the 4 CENTER columns per row (Rc[4][4], 16 regs);
//      the 8 halo columns of rows e-1,e,e+1 are re-loaded each step (L1 hits),
//      freeing 32 persistent registers -> 6 blocks/SM.
//  (b) zero-page trick: all conditional loads become unconditional LDGs whose
//      BASE POINTER is pre-selected between the image and a __device__ zero
//      buffer (okL/okR once per thread; ntop/nbot only at literal boundary
//      steps). No per-load predicates, no zero-MOV fills.
//  - K1 = S(x)S - 2 D(x)D  via P = 2*mid - DY:  E[j] = P[j]+P[j+2]+2*SY[j+1]
//  - K2 = A(x)r0 + B(x)r1  (A=[1,0,-2,0,1], B=[0,1,-2,1,0],
//         r0=[-1,2,-2,2,-1], r1=[2,-6,8,-6,2]) -> H0/Hh + vertical scatter
//  - K3 = [1,-2,1] horizontal at finalize (tex x-edge zeroing via okL/okR)

#define IMG  512
#define BAND 32
#define NTH  128

// Zero page: covers halo/center offsets rel 0..37 (+/-4 cols). Device globals
// are zero-initialized; never written -> stays zero (graph-replay safe).
__device__ __align__(16) float ZBUF[38 * 512 + 16];

#define LOADC(SLOT, REL, BP) do {                                               \
    float4 _c4 = *reinterpret_cast<const float4*>((BP) + (REL) * IMG);          \
    Rc[SLOT][0]=_c4.x; Rc[SLOT][1]=_c4.y; Rc[SLOT][2]=_c4.z; Rc[SLOT][3]=_c4.w; \
} while (0)

// One pipeline step. T literal. TA slots U,S1..S4 = (T..T+4)%5 literals.
// Rc slots RA,RB,RX = center rows e-1,e,e+1 = (T..T+2)%4; RD = (T+3)%4 gets
// center of row e+2 from base BC. BL0/BR0..BL2/BR2: halo bases rows e-1..e+1.
#define STEP(T, U,S1,S2,S3,S4, RA,RB,RX,RD, BC, BL0,BR0, BL1,BR1, BL2,BR2, EV) do { \
    if ((T) <= 34) LOADC(RD, (T)+3, BC);          /* prefetch center row e+2 */ \
    float4 l0 = *reinterpret_cast<const float4*>((BL0) + ((T)  ) * IMG);        \
    float4 r0 = *reinterpret_cast<const float4*>((BR0) + ((T)  ) * IMG);        \
    float4 l1 = *reinterpret_cast<const float4*>((BL1) + ((T)+1) * IMG);        \
    float4 r1 = *reinterpret_cast<const float4*>((BR1) + ((T)+1) * IMG);        \
    float4 l2 = *reinterpret_cast<const float4*>((BL2) + ((T)+2) * IMG);        \
    float4 r2 = *reinterpret_cast<const float4*>((BR2) + ((T)+2) * IMG);        \
    if (EV) {                                                                   \
        const float X0[12] = {l0.x,l0.y,l0.z,l0.w,                              \
            Rc[RA][0],Rc[RA][1],Rc[RA][2],Rc[RA][3], r0.x,r0.y,r0.z,r0.w};      \
        const float X1[12] = {l1.x,l1.y,l1.z,l1.w,                              \
            Rc[RB][0],Rc[RB][1],Rc[RB][2],Rc[RB][3], r1.x,r1.y,r1.z,r1.w};      \
        const float X2[12] = {l2.x,l2.y,l2.z,l2.w,                              \
            Rc[RX][0],Rc[RX][1],Rc[RX][2],Rc[RX][3], r2.x,r2.y,r2.z,r2.w};      \
        float DY[12], P[12], SY[12], E[10];                                     \
        _Pragma("unroll")                                                       \
        for (int c = 0; c < 12; c++) {                                          \
            DY[c] = fmaf(1.f, X0[c], X2[c]);                                    \
            P[c]  = fmaf(2.f, X1[c], -DY[c]);   /* = SY - 2*DY */               \
        }                                                                       \
        _Pragma("unroll")                                                       \
        for (int c = 1; c < 11; c++)                                            \
            SY[c] = fmaf(2.f, X1[c], DY[c]);                                    \
        _Pragma("unroll")                                                       \
        for (int j = 0; j < 10; j++) {                                          \
            float t = fmaf(1.f, P[j], P[j+2]);                                  \
            E[j] = fmaf(2.f, SY[j+1], t);                                       \
        }                                                                       \
        if (tid == 0)          { E[0] = 0.f; E[1] = 0.f; E[2] = 0.f; }          \
        else if (tid == NTH-1) { E[7] = 0.f; E[8] = 0.f; E[9] = 0.f; }          \
        _Pragma("unroll")                                                       \
        for (int c = 0; c < 6; c++) {                                           \
            float s1 = fmaf(1.f, E[c],   E[c+4]);                               \
            float s2 = fmaf(1.f, E[c+1], E[c+3]);                               \
            float H0 = fmaf(-2.f, E[c+2], fmaf( 2.f, s2, -s1));                 \
            float Hh = fmaf( 4.f, E[c+2], fmaf(-3.f, s2,  s1)); /* H1/2 */      \
            TA[U][c]  = fmaf( 1.f, H0, TA[U][c]);              /* y=e-2 */      \
            TA[S1][c] = fmaf( 2.f, Hh, TA[S1][c]);             /* y=e-1 */      \
            TA[S2][c] = fmaf(-2.f, H0, fmaf(-4.f, Hh, TA[S2][c])); /* y=e */    \
            TA[S3][c] = fmaf( 2.f, Hh, TA[S3][c]);             /* y=e+1 */      \
            TA[S4][c] = H0;            /* first touch of row y=e+2: assign */   \
        }                                                                       \
    } else {                                                                    \
        _Pragma("unroll")                                                       \
        for (int c = 0; c < 6; c++) TA[S4][c] = 0.f;  /* edge row is zero */    \
    }                                                                           \
    if ((T) >= 4) {   /* K3 + store output row y = Y0-4+T from slot U */        \
        float tv0 = okL ? TA[U][0] : 0.f;      /* tex zero-pad at x edges */    \
        float tv5 = okR ? TA[U][5] : 0.f;                                       \
        float4 o;                                                               \
        o.x = fmaf(-2.f, TA[U][1], fmaf(1.f, tv0,      TA[U][2]));              \
        o.y = fmaf(-2.f, TA[U][2], fmaf(1.f, TA[U][1], TA[U][3]));              \
        o.z = fmaf(-2.f, TA[U][3], fmaf(1.f, TA[U][2], TA[U][4]));              \
        o.w = fmaf(-2.f, TA[U][4], fmaf(1.f, TA[U][3], tv5));                   \
        *reinterpret_cast<float4*>(op + (long)((T) - 4) * IMG) = o;             \
    }                                                                           \
} while (0)

#define TSEL(p) (ntop ? (p) : zb)
#define BSEL(p) (nbot ? (p) : zb)

__global__ __launch_bounds__(NTH, 6)
void rf_kernel(const float* __restrict__ x, float* __restrict__ out)
{
    const int tid = threadIdx.x;
    const int Y0  = (int)blockIdx.x * BAND;
    const long base = (long)blockIdx.y * (IMG * IMG);
    const int cx  = tid * 4;
    const bool okL = (tid != 0);
    const bool okR = (tid != NTH - 1);
    const bool ntop = (Y0 != 0);               // rows above band exist
    const bool nbot = (Y0 != IMG - BAND);      // rows below band exist

    float Rc[4][4];    // center-col ring: slot(rel r) = r % 4, rel = row-(Y0-3)
    float TA[5][6];    // tex accumulator ring: 5 rows x 6 cols (cx-1..cx+4)

    const float* zb = ZBUF + 8;
    const float* bC = x + base + (long)(Y0 - 3) * IMG + cx;   // center base
    const float* bL = okL ? bC - 4 : zb;                      // left-halo base
    const float* bR = okR ? bC + 4 : zb;                      // right-halo base
    float* op = out + base + (long)Y0 * IMG + cx;

    // prime centers of rows Y0-3..Y0-1 -> slots 0..2 (step 0 prefetches Y0)
    LOADC(0, 0, TSEL(bC));
    LOADC(1, 1, TSEL(bC));
    LOADC(2, 2, TSEL(bC));

    STEP( 0, 0,1,2,3,4, 0,1,2,3, bC, TSEL(bL),TSEL(bR), TSEL(bL),TSEL(bR), TSEL(bL),TSEL(bR), ntop);
    STEP( 1, 1,2,3,4,0, 1,2,3,0, bC, TSEL(bL),TSEL(bR), TSEL(bL),TSEL(bR), bL,bR,             ntop);
    STEP( 2, 2,3,4,0,1, 2,3,0,1, bC, TSEL(bL),TSEL(bR), bL,bR,             bL,bR,             true);
    STEP( 3, 3,4,0,1,2, 3,0,1,2, bC, bL,bR, bL,bR, bL,bR, true);
    STEP( 4, 4,0,1,2,3, 0,1,2,3, bC, bL,bR, bL,bR, bL,bR, true);
    STEP( 5, 0,1,2,3,4, 1,2,3,0, bC, bL,bR, bL,bR, bL,bR, true);
    STEP( 6, 1,2,3,4,0, 2,3,0,1, bC, bL,bR, bL,bR, bL,bR, true);
    STEP( 7, 2,3,4,0,1, 3,0,1,2, bC, bL,bR, bL,bR, bL,bR, true);
    STEP( 8, 3,4,0,1,2, 0,1,2,3, bC, bL,bR, bL,bR, bL,bR, true);
    STEP( 9, 4,0,1,2,3, 1,2,3,0, bC, bL,bR, bL,bR, bL,bR, true);
    STEP(10, 0,1,2,3,4, 2,3,0,1, bC, bL,bR, bL,bR, bL,bR, true);
    STEP(11, 1,2,3,4,0, 3,0,1,2, bC, bL,bR, bL,bR, bL,bR, true);
    STEP(12, 2,3,4,0,1, 0,1,2,3, bC, bL,bR, bL,bR, bL,bR, true);
    STEP(13, 3,4,0,1,2, 1,2,3,0, bC, bL,bR, bL,bR, bL,bR, true);
    STEP(14, 4,0,1,2,3, 2,3,0,1, bC, bL,bR, bL,bR, bL,bR, true);
    STEP(15, 0,1,2,3,4, 3,0,1,2, bC, bL,bR, bL,bR, bL,bR, true);
    STEP(16, 1,2,3,4,0, 0,1,2,3, bC, bL,bR, bL,bR, bL,bR, true);
    STEP(17, 2,3,4,0,1, 1,2,3,0, bC, bL,bR, bL,bR, bL,bR, true);
    STEP(18, 3,4,0,1,2, 2,3,0,1, bC, bL,bR, bL,bR, bL,bR, true);
    STEP(19, 4,0,1,2,3, 3,0,1,2, bC, bL,bR, bL,bR, bL,bR, true);
    STEP(20, 0,1,2,3,4, 0,1,2,3, bC, bL,bR, bL,bR, bL,bR, true);
    STEP(21, 1,2,3,4,0, 1,2,3,0, bC, bL,bR, bL,bR, bL,bR, true);
    STEP(22, 2,3,4,0,1, 2,3,0,1, bC, bL,bR, bL,bR, bL,bR, true);
    STEP(23, 3,4,0,1,2, 3,0,1,2, bC, bL,bR, bL,bR, bL,bR, true);
    STEP(24, 4,0,1,2,3, 0,1,2,3, bC, bL,bR, bL,bR, bL,bR, true);
    STEP(25, 0,1,2,3,4, 1,2,3,0, bC, bL,bR, bL,bR, bL,bR, true);
    STEP(26, 1,2,3,4,0, 2,3,0,1, bC, bL,bR, bL,bR, bL,bR, true);
    STEP(27, 2,3,4,0,1, 3,0,1,2, bC, bL,bR, bL,bR, bL,bR, true);
    STEP(28, 3,4,0,1,2, 0,1,2,3, bC, bL,bR, bL,bR, bL,bR, true);
    STEP(29, 4,0,1,2,3, 1,2,3,0, bC, bL,bR, bL,bR, bL,bR, true);
    STEP(30, 0,1,2,3,4, 2,3,0,1, bC, bL,bR, bL,bR, bL,bR, true);
    STEP(31, 1,2,3,4,0, 3,0,1,2, bC, bL,bR, bL,bR, bL,bR, true);
    STEP(32, 2,3,4,0,1, 0,1,2,3, BSEL(bC), bL,bR, bL,bR, bL,bR,                         true);
    STEP(33, 3,4,0,1,2, 1,2,3,0, BSEL(bC), bL,bR, bL,bR, BSEL(bL),BSEL(bR),             true);
    STEP(34, 4,0,1,2,3, 2,3,0,1, BSEL(bC), bL,bR, BSEL(bL),BSEL(bR), BSEL(bL),BSEL(bR), nbot);
    STEP(35, 0,1,2,3,4, 3,0,1,2, bC /*no load*/, BSEL(bL),BSEL(bR), BSEL(bL),BSEL(bR), BSEL(bL),BSEL(bR), nbot);
}

extern "C" void kernel_launch(void* const* d_in, const int* in_sizes, int n_in,
                              void* d_out, int out_size)
{
    const float* x = (const float*)d_in[0];
    float* out = (float*)d_out;
    const int planes = in_sizes[0] / (IMG * IMG);   // 64*3 = 192

    dim3 grid(IMG / BAND, planes);                  // (16, 192) = 3072 blocks
    rf_kernel<<<grid, NTH>>>(x, out);
}